// round 16
// baseline (speedup 1.0000x reference)
#include <cuda_runtime.h>
#include <math.h>
#include <stdint.h>

// Problem constants
#define BSZ   4
#define NQ    2048
#define MK    2048
#define DIMX  1024
#define CTXD  1024
#define HEADS 8
#define DHEAD 64
#define INNER 512   // HEADS * DHEAD

// ============================================================================
// Packed bf16 hi/lo scratch in gmem (allocation-free: __device__ globals)
// ============================================================================
__device__ uint32_t g_xH[(size_t)8192 * 512], g_xL[(size_t)8192 * 512];
__device__ uint32_t g_cH[(size_t)8192 * 512], g_cL[(size_t)8192 * 512];
__device__ uint32_t g_WqH[512 * 512],  g_WqL[512 * 512];
__device__ uint32_t g_WkH[512 * 512],  g_WkL[512 * 512];
__device__ uint32_t g_WvH[512 * 512],  g_WvL[512 * 512];
__device__ uint32_t g_WoH[1024 * 256], g_WoL[1024 * 256];
__device__ uint32_t g_QH[(size_t)32 * 2048 * 32], g_QL[(size_t)32 * 2048 * 32];
__device__ uint32_t g_KH[(size_t)32 * 2048 * 32], g_KL[(size_t)32 * 2048 * 32];
__device__ uint32_t g_VH[(size_t)32 * 2048 * 32], g_VL[(size_t)32 * 2048 * 32];
__device__ uint32_t g_OH2[(size_t)8192 * 256], g_OL2[(size_t)8192 * 256];
__device__ int      g_idx[BSZ * MK];
__device__ int      g_cnt[BSZ];

// ============================================================================
// bf16 x3 helpers, ldmatrix, cp.async
// ============================================================================
__device__ __forceinline__ uint32_t pack_bf16x2(float e0, float e1) {
    uint32_t r;
    asm("cvt.rn.bf16x2.f32 %0, %1, %2;" : "=r"(r) : "f"(e1), "f"(e0));
    return r;
}
__device__ __forceinline__ void split_pair(float x0, float x1,
                                           uint32_t& hi, uint32_t& lo) {
    hi = pack_bf16x2(x0, x1);
    float h0 = __uint_as_float(hi << 16);
    float h1 = __uint_as_float(hi & 0xffff0000u);
    lo = pack_bf16x2(x0 - h0, x1 - h1);
}
__device__ __forceinline__ void mmabf(float c[4], const uint32_t a[4],
                                      const uint32_t b[2]) {
    asm volatile(
        "mma.sync.aligned.m16n8k16.row.col.f32.bf16.bf16.f32 "
        "{%0,%1,%2,%3},{%4,%5,%6,%7},{%8,%9},{%0,%1,%2,%3};"
        : "+f"(c[0]), "+f"(c[1]), "+f"(c[2]), "+f"(c[3])
        : "r"(a[0]), "r"(a[1]), "r"(a[2]), "r"(a[3]), "r"(b[0]), "r"(b[1]));
}
__device__ __forceinline__ void mmabf_x3(float c[4],
                                         const uint32_t aH[4], const uint32_t aL[4],
                                         const uint32_t bH[2], const uint32_t bL[2]) {
    mmabf(c, aH, bH);
    mmabf(c, aH, bL);
    mmabf(c, aL, bH);
}
__device__ __forceinline__ void ldsm_x4(uint32_t* r, uint32_t a) {
    asm volatile("ldmatrix.sync.aligned.m8n8.x4.shared.b16 {%0,%1,%2,%3}, [%4];"
                 : "=r"(r[0]), "=r"(r[1]), "=r"(r[2]), "=r"(r[3]) : "r"(a));
}
__device__ __forceinline__ void ldsm_x2(uint32_t* r, uint32_t a) {
    asm volatile("ldmatrix.sync.aligned.m8n8.x2.shared.b16 {%0,%1}, [%2];"
                 : "=r"(r[0]), "=r"(r[1]) : "r"(a));
}
__device__ __forceinline__ void ldsm_x2_t(uint32_t* r, uint32_t a) {
    asm volatile("ldmatrix.sync.aligned.m8n8.x2.trans.shared.b16 {%0,%1}, [%2];"
                 : "=r"(r[0]), "=r"(r[1]) : "r"(a));
}
__device__ __forceinline__ uint32_t smem_u32(const void* p) {
    uint32_t a;
    asm("{ .reg .u64 t; cvta.to.shared.u64 t, %1; cvt.u32.u64 %0, t; }"
        : "=r"(a) : "l"(p));
    return a;
}
__device__ __forceinline__ void cpa16(uint32_t sa, const void* g) {
    asm volatile("cp.async.cg.shared.global [%0], [%1], 16;"
                 :: "r"(sa), "l"(g) : "memory");
}
__device__ __forceinline__ void cpa16z(uint32_t sa, const void* g, bool valid) {
    int sz = valid ? 16 : 0;
    asm volatile("cp.async.cg.shared.global [%0], [%1], 16, %2;"
                 :: "r"(sa), "l"(g), "r"(sz) : "memory");
}
#define CP_COMMIT() asm volatile("cp.async.commit_group;" ::: "memory")
#define CP_WAIT1()  asm volatile("cp.async.wait_group 1;"  ::: "memory")
#define CP_WAIT0()  asm volatile("cp.async.wait_group 0;"  ::: "memory")

// ============================================================================
// prep_kernel: ONE launch covering all independent preprocessing.
// ============================================================================
#define PREP_C0  8192
#define PREP_WQ  16384
#define PREP_WK  16448
#define PREP_WV  16512
#define PREP_WO  16576
#define PREP_CM  16640
#define PREP_NB  16644

__device__ __forceinline__ void repack_a_body(const float* __restrict__ A,
                                              uint32_t* __restrict__ H,
                                              uint32_t* __restrict__ L,
                                              int blk, int tid)
{
    int i = blk * 256 + tid;
    float4 a = ((const float4*)A)[i];
    uint32_t h0, l0, h1, l1;
    split_pair(a.x, a.y, h0, l0);
    split_pair(a.z, a.w, h1, l1);
    H[2 * i] = h0; H[2 * i + 1] = h1;
    L[2 * i] = l0; L[2 * i + 1] = l1;
}

__device__ __forceinline__ void repack_w_body(const float* __restrict__ W,
                                              uint32_t* __restrict__ H,
                                              uint32_t* __restrict__ L,
                                              int K, int N, int k0, int n0,
                                              float SM[128][68], int tid)
{
    #pragma unroll
    for (int j = 0; j < 8; j++) {
        int idx = tid + j * 256;
        int r = idx >> 4, c4 = (idx & 15) * 4;
        *(float4*)&SM[r][c4] = *(const float4*)(W + (size_t)(k0 + r) * N + n0 + c4);
    }
    __syncthreads();
    #pragma unroll
    for (int j = 0; j < 16; j++) {
        int idx = tid + j * 256;
        int n = idx >> 6, kp = idx & 63;
        uint32_t h, l;
        split_pair(SM[2 * kp][n], SM[2 * kp + 1][n], h, l);
        size_t d = (size_t)(n0 + n) * (K / 2) + k0 / 2 + kp;
        H[d] = h; L[d] = l;
    }
}

__global__ __launch_bounds__(256)
void prep_kernel(const float* __restrict__ x, const float* __restrict__ ctx,
                 const int* __restrict__ mask,
                 const float* __restrict__ Wq, const float* __restrict__ Wk,
                 const float* __restrict__ Wv, const float* __restrict__ Wo,
                 uint32_t* xH, uint32_t* xL, uint32_t* cH, uint32_t* cL,
                 uint32_t* WqH, uint32_t* WqL, uint32_t* WkH, uint32_t* WkL,
                 uint32_t* WvH, uint32_t* WvL, uint32_t* WoH, uint32_t* WoL,
                 int* __restrict__ idxOut, int* __restrict__ cntOut)
{
    __shared__ float SM[128][68];
    const int bid = blockIdx.x, tid = threadIdx.x;

    if (bid < PREP_C0) {
        repack_a_body(x, xH, xL, bid, tid);
    } else if (bid < PREP_WQ) {
        repack_a_body(ctx, cH, cL, bid - PREP_C0, tid);
    } else if (bid < PREP_WK) {
        int b = bid - PREP_WQ;
        repack_w_body(Wq, WqH, WqL, 1024, 512, (b & 7) * 128, (b >> 3) * 64, SM, tid);
    } else if (bid < PREP_WV) {
        int b = bid - PREP_WK;
        repack_w_body(Wk, WkH, WkL, 1024, 512, (b & 7) * 128, (b >> 3) * 64, SM, tid);
    } else if (bid < PREP_WO) {
        int b = bid - PREP_WV;
        repack_w_body(Wv, WvH, WvL, 1024, 512, (b & 7) * 128, (b >> 3) * 64, SM, tid);
    } else if (bid < PREP_CM) {
        int b = bid - PREP_WO;
        repack_w_body(Wo, WoH, WoL, 512, 1024, (b & 3) * 128, (b >> 2) * 64, SM, tid);
    } else {
        // compact_mask body (1 block per batch)
        int* ws = (int*)&SM[0][0];
        const int b = bid - PREP_CM;
        const int lane = tid & 31, w = tid >> 5;
        const int* mb = mask + b * MK;
        int loc[8], c = 0;
        #pragma unroll
        for (int j = 0; j < 8; j++) {
            loc[j] = (mb[tid * 8 + j] != 0);
            c += loc[j];
        }
        int pre = c;
        #pragma unroll
        for (int off = 1; off < 32; off <<= 1) {
            int v = __shfl_up_sync(0xffffffffu, pre, off);
            if (lane >= off) pre += v;
        }
        if (lane == 31) ws[w] = pre;
        __syncthreads();
        if (tid == 0) {
            int s = 0;
            #pragma unroll
            for (int i = 0; i < 8; i++) { int t2 = ws[i]; ws[i] = s; s += t2; }
            cntOut[b] = s;
        }
        __syncthreads();
        int start = ws[w] + pre - c;
        #pragma unroll
        for (int j = 0; j < 8; j++)
            if (loc[j]) idxOut[b * MK + start++] = tid * 8 + j;
    }
}

// ============================================================================
// Shared GEMM mainloop pieces (BM=128, BN=128, BK=32; 256 thr, warp 32x64)
// ============================================================================
#define GB 10240   // words per stage buffer

struct GemmCtx {
    uint32_t smb;
    int tid, lane, warp, wm, wn, g, t;
    int arow_sel, acol_sel, brow_sel, bcol_sel;
    int srow, sseg;
};
__device__ __forceinline__ void gemm_init(GemmCtx& c) {
    c.tid = threadIdx.x;
    c.lane = c.tid & 31; c.warp = c.tid >> 5;
    c.wm = c.warp & 3; c.wn = c.warp >> 2;
    c.g = c.lane >> 2; c.t = c.lane & 3;
    c.arow_sel = (c.lane & 7) + (c.lane & 8);
    c.acol_sel = (c.lane & 16) ? 4 : 0;
    c.brow_sel = c.lane & 7;
    c.bcol_sel = (c.lane & 8) ? 4 : 0;
    c.srow = c.tid >> 2; c.sseg = c.tid & 3;
}
__device__ __forceinline__ void gemm_stage(const GemmCtx& c,
                                           const uint32_t* AH, const uint32_t* AL,
                                           const uint32_t* BH, const uint32_t* BL,
                                           int m0, int n0, int Kw,
                                           int buf, int k0) {
    const int base = buf * GB;
    #pragma unroll
    for (int j = 0; j < 2; j++) {
        const int row = c.srow + j * 64;
        const uint32_t sa = c.smb + (uint32_t)((base + row * 20 + c.sseg * 4) * 4);
        const size_t ga = (size_t)(m0 + row) * Kw + (k0 >> 1) + c.sseg * 4;
        cpa16(sa, AH + ga);
        cpa16(sa + 2560 * 4, AL + ga);
        const size_t gb = (size_t)(n0 + row) * Kw + (k0 >> 1) + c.sseg * 4;
        cpa16(sa + 5120 * 4, BH + gb);
        cpa16(sa + 7680 * 4, BL + gb);
    }
}
__device__ __forceinline__ void gemm_mainloop(const GemmCtx& c,
                                              const uint32_t* AH, const uint32_t* AL,
                                              const uint32_t* BH, const uint32_t* BL,
                                              int m0, int n0, int K,
                                              float acc[2][8][4]) {
    const int Kw = K >> 1;
    #pragma unroll
    for (int mt = 0; mt < 2; mt++)
        #pragma unroll
        for (int nt = 0; nt < 8; nt++)
            #pragma unroll
            for (int i = 0; i < 4; i++) acc[mt][nt][i] = 0.f;

    gemm_stage(c, AH, AL, BH, BL, m0, n0, Kw, 0, 0);
    CP_COMMIT();

    int buf = 0;
    for (int k0 = 0; k0 < K; k0 += 32) {
        if (k0 + 32 < K) {
            gemm_stage(c, AH, AL, BH, BL, m0, n0, Kw, buf ^ 1, k0 + 32);
            CP_COMMIT();
            CP_WAIT1();
        } else {
            CP_WAIT0();
        }
        __syncthreads();

        const int base = buf * GB;
        #pragma unroll
        for (int s = 0; s < 2; s++) {
            uint32_t aH[2][4], aL[2][4];
            #pragma unroll
            for (int mt = 0; mt < 2; mt++) {
                const uint32_t aoff = c.smb +
                    (uint32_t)((base + (c.wm * 32 + mt * 16 + c.arow_sel) * 20 +
                                s * 8 + c.acol_sel) * 4);
                ldsm_x4(aH[mt], aoff);
                ldsm_x4(aL[mt], aoff + 2560 * 4);
            }
            #pragma unroll
            for (int nt = 0; nt < 8; nt++) {
                const uint32_t boff = c.smb +
                    (uint32_t)((base + (c.wn * 64 + nt * 8 + c.brow_sel) * 20 +
                                s * 8 + c.bcol_sel) * 4);
                uint32_t bH[2], bL[2];
                ldsm_x2(bH, boff + 5120 * 4);
                ldsm_x2(bL, boff + 7680 * 4);
                mmabf_x3(acc[0][nt], aH[0], aL[0], bH, bL);
                mmabf_x3(acc[1][nt], aH[1], aL[1], bH, bL);
            }
        }
        __syncthreads();
        buf ^= 1;
    }
}

// ============================================================================
// proj_kernel: ONE launch for all 3 projections (blockIdx.z = 0:Q, 1:K, 2:V).
// ALL epilogues -> packed [b,h][tok][dpair].
// grid (512/128, 8192/128, 3)
// ============================================================================
__global__ __launch_bounds__(256, 2)
void proj_kernel(const uint32_t* __restrict__ xH, const uint32_t* __restrict__ xL,
                 const uint32_t* __restrict__ cH, const uint32_t* __restrict__ cL,
                 const uint32_t* __restrict__ WqH, const uint32_t* __restrict__ WqL,
                 const uint32_t* __restrict__ WkH, const uint32_t* __restrict__ WkL,
                 const uint32_t* __restrict__ WvH, const uint32_t* __restrict__ WvL,
                 uint32_t* __restrict__ QH, uint32_t* __restrict__ QL,
                 uint32_t* __restrict__ KH, uint32_t* __restrict__ KL,
                 uint32_t* __restrict__ VH, uint32_t* __restrict__ VL)
{
    extern __shared__ uint32_t gs[];
    GemmCtx c;
    gemm_init(c);
    c.smb = smem_u32(gs);

    const int z = blockIdx.z;
    const int m0 = blockIdx.y * 128, n0 = blockIdx.x * 128;
    const uint32_t *AH, *AL, *BH, *BL;
    if (z == 0)      { AH = xH; AL = xL; BH = WqH; BL = WqL; }
    else if (z == 1) { AH = cH; AL = cL; BH = WkH; BL = WkL; }
    else             { AH = cH; AL = cL; BH = WvH; BL = WvL; }

    float acc[2][8][4];
    gemm_mainloop(c, AH, AL, BH, BL, m0, n0, 1024, acc);

    uint32_t* OH = (z == 0) ? QH : ((z == 1) ? KH : VH);
    uint32_t* OL = (z == 0) ? QL : ((z == 1) ? KL : VL);
    #pragma unroll
    for (int mt = 0; mt < 2; mt++) {
        const int r0 = m0 + c.wm * 32 + mt * 16 + c.g;
        const int b = r0 >> 11;
        #pragma unroll
        for (int nt = 0; nt < 8; nt++) {
            const int c0 = n0 + c.wn * 64 + nt * 8 + c.t * 2;
            const int h = c0 >> 6, w = (c0 & 63) >> 1;
            uint32_t hh, ll;
            split_pair(acc[mt][nt][0], acc[mt][nt][1], hh, ll);
            size_t d0 = ((size_t)(b * 8 + h) * 2048 + (r0 & 2047)) * 32 + w;
            OH[d0] = hh; OL[d0] = ll;
            split_pair(acc[mt][nt][2], acc[mt][nt][3], hh, ll);
            size_t d1 = d0 + 8 * 32;
            OH[d1] = hh; OL[d1] = ll;
        }
    }
}

// ============================================================================
// out_gemm: out = O @ Wo + bo (packed operands), fp32 out.
// grid (1024/128, 8192/128)
// ============================================================================
__global__ __launch_bounds__(256, 2)
void out_gemm(const uint32_t* __restrict__ AH, const uint32_t* __restrict__ AL,
              const uint32_t* __restrict__ BH, const uint32_t* __restrict__ BL,
              float* __restrict__ C, const float* __restrict__ bias)
{
    extern __shared__ uint32_t gs[];
    GemmCtx c;
    gemm_init(c);
    c.smb = smem_u32(gs);
    const int m0 = blockIdx.y * 128, n0 = blockIdx.x * 128;

    float acc[2][8][4];
    gemm_mainloop(c, AH, AL, BH, BL, m0, n0, 512, acc);

    #pragma unroll
    for (int mt = 0; mt < 2; mt++) {
        const int r0 = m0 + c.wm * 32 + mt * 16 + c.g;
        #pragma unroll
        for (int nt = 0; nt < 8; nt++) {
            const int c0 = n0 + c.wn * 64 + nt * 8 + c.t * 2;
            float b0v = bias[c0], b1v = bias[c0 + 1];
            *(float2*)(C + (size_t)r0 * 1024 + c0) =
                make_float2(acc[mt][nt][0] + b0v, acc[mt][nt][1] + b1v);
            *(float2*)(C + (size_t)(r0 + 8) * 1024 + c0) =
                make_float2(acc[mt][nt][2] + b0v, acc[mt][nt][3] + b1v);
        }
    }
}

// ============================================================================
// flash_cp: bf16 x3, P in registers, cp.async double-buffered, compacted keys.
// K AND V both gathered by idx in token layout [b,h][tok][dpair]; V fragments
// loaded via ldmatrix.trans (transpose at load, no repack kernel).
// Smem words: Qh[0..4607] Ql[4608..9215]; per buf (9216 + buf*9216):
//   Kh +0, Kl +2304, Vh +4608, Vl +6912 (each 64 rows x 36 stride).
// ============================================================================
#define FL_KV    9216
#define FL_BUF   9216
#define FLASH_SMEM_BYTES ((FL_KV + 2 * FL_BUF) * 4)

__global__ __launch_bounds__(256, 2)
void flash_cp(const uint32_t* __restrict__ QHg, const uint32_t* __restrict__ QLg,
              const uint32_t* __restrict__ KHg, const uint32_t* __restrict__ KLg,
              const uint32_t* __restrict__ VHg, const uint32_t* __restrict__ VLg,
              const int* __restrict__ idx, const int* __restrict__ cnt,
              uint32_t* __restrict__ OH, uint32_t* __restrict__ OL)
{
    extern __shared__ uint32_t fsm[];
    const uint32_t smb = smem_u32(fsm);

    const int bh = blockIdx.y;
    const int b = bh >> 3, h = bh & 7;
    const int q0 = blockIdx.x * 128;

    const int tid = threadIdx.x;
    const int lane = tid & 31, warp = tid >> 5;
    const int g = lane >> 2, t = lane & 3;
    const int pr = warp * 16;

    const int arow_sel = (lane & 7) + (lane & 8);
    const int acol_sel = (lane & 16) ? 4 : 0;
    const int brow_sel = lane & 7;
    const int bcol_sel = (lane & 8) ? 4 : 0;
    const int trow_sel = lane & 15;          // trans ldmatrix row (keys)

    const int cntb = cnt[b];
    const int Mp = (cntb + 63) & ~63;
    const int* gidx = idx + b * MK;

    auto stageKV = [&](int nb, int kt2) {
        const int base = FL_KV + nb * FL_BUF;
        #pragma unroll
        for (int j = 0; j < 2; j++) {
            const int i2 = tid + j * 256;
            const int r = i2 >> 3, sg = i2 & 7;
            const int tok_i = kt2 + r;
            const bool valid = tok_i < cntb;
            const int tok = valid ? gidx[tok_i] : 0;
            const uint32_t sa = smb + (uint32_t)((base + r * 36 + sg * 4) * 4);
            const size_t gk = ((size_t)bh * 2048 + tok) * 32 + sg * 4;
            cpa16z(sa, KHg + gk, valid);
            cpa16z(sa + 2304 * 4, KLg + gk, valid);
            cpa16z(sa + 4608 * 4, VHg + gk, valid);   // V: same layout as K
            cpa16z(sa + 6912 * 4, VLg + gk, valid);
        }
    };

    // prologue: stage Q + tile 0
    #pragma unroll
    for (int j = 0; j < 4; j++) {
        const int i2 = tid + j * 256;
        const int row = i2 >> 3, seg = i2 & 7;
        const uint32_t sa = smb + (uint32_t)((row * 36 + seg * 4) * 4);
        const size_t gq = ((size_t)bh * 2048 + q0 + row) * 32 + seg * 4;
        cpa16(sa, QHg + gq);
        cpa16(sa + 4608 * 4, QLg + gq);
    }
    stageKV(0, 0);
    CP_COMMIT();

    float of[8][4];
    #pragma unroll
    for (int nt = 0; nt < 8; nt++)
        #pragma unroll
        for (int i = 0; i < 4; i++) of[nt][i] = 0.f;
    float mrow0 = -3.0e38f, mrow1 = -3.0e38f, lrow0 = 0.f, lrow1 = 0.f;
    const float scale = 0.125f;

    int buf = 0;
    for (int kt = 0; kt < Mp; kt += 64) {
        if (kt + 64 < Mp) {
            stageKV(buf ^ 1, kt + 64);
            CP_COMMIT();
            CP_WAIT1();
        } else {
            CP_WAIT0();
        }
        __syncthreads();

        const int base = FL_KV + buf * FL_BUF;
        const int limit = cntb - kt;

        // ---- S = Q K^T ----
        float sf[8][4];
        #pragma unroll
        for (int nt = 0; nt < 8; nt++)
            #pragma unroll
            for (int i = 0; i < 4; i++) sf[nt][i] = 0.f;

        #pragma unroll
        for (int s = 0; s < 4; s++) {
            uint32_t aH[4], aL[4];
            const uint32_t qoff = smb +
                (uint32_t)(((pr + arow_sel) * 36 + s * 8 + acol_sel) * 4);
            ldsm_x4(aH, qoff);
            ldsm_x4(aL, qoff + 4608 * 4);
            #pragma unroll
            for (int nt = 0; nt < 8; nt++) {
                const uint32_t koff = smb +
                    (uint32_t)((base + (nt * 8 + brow_sel) * 36 + s * 8 + bcol_sel) * 4);
                uint32_t bH[2], bL[2];
                ldsm_x2(bH, koff);
                ldsm_x2(bL, koff + 2304 * 4);
                mmabf_x3(sf[nt], aH, aL, bH, bL);
            }
        }

        // ---- scale + validity + online softmax ----
        float mx0 = -3.0e38f, mx1 = -3.0e38f;
        #pragma unroll
        for (int nt = 0; nt < 8; nt++) {
            const int c0 = nt * 8 + 2 * t;
            float mk0 = (c0     < limit) ? 0.f : -1.0e30f;
            float mk1 = (c0 + 1 < limit) ? 0.f : -1.0e30f;
            sf[nt][0] = sf[nt][0] * scale + mk0;
            sf[nt][1] = sf[nt][1] * scale + mk1;
            sf[nt][2] = sf[nt][2] * scale + mk0;
            sf[nt][3] = sf[nt][3] * scale + mk1;
            mx0 = fmaxf(mx0, fmaxf(sf[nt][0], sf[nt][1]));
            mx1 = fmaxf(mx1, fmaxf(sf[nt][2], sf[nt][3]));
        }
        mx0 = fmaxf(mx0, __shfl_xor_sync(0xffffffffu, mx0, 1));
        mx0 = fmaxf(mx0, __shfl_xor_sync(0xffffffffu, mx0, 2));
        mx1 = fmaxf(mx1, __shfl_xor_sync(0xffffffffu, mx1, 1));
        mx1 = fmaxf(mx1, __shfl_xor_sync(0xffffffffu, mx1, 2));

        const float mn0 = fmaxf(mrow0, mx0), mn1 = fmaxf(mrow1, mx1);
        const float corr0 = __expf(mrow0 - mn0), corr1 = __expf(mrow1 - mn1);
        float ls0 = 0.f, ls1 = 0.f;
        #pragma unroll
        for (int nt = 0; nt < 8; nt++) {
            sf[nt][0] = __expf(sf[nt][0] - mn0);
            sf[nt][1] = __expf(sf[nt][1] - mn0);
            sf[nt][2] = __expf(sf[nt][2] - mn1);
            sf[nt][3] = __expf(sf[nt][3] - mn1);
            ls0 += sf[nt][0] + sf[nt][1];
            ls1 += sf[nt][2] + sf[nt][3];
        }
        ls0 += __shfl_xor_sync(0xffffffffu, ls0, 1);
        ls0 += __shfl_xor_sync(0xffffffffu, ls0, 2);
        ls1 += __shfl_xor_sync(0xffffffffu, ls1, 1);
        ls1 += __shfl_xor_sync(0xffffffffu, ls1, 2);

        lrow0 = lrow0 * corr0 + ls0; mrow0 = mn0;
        lrow1 = lrow1 * corr1 + ls1; mrow1 = mn1;

        #pragma unroll
        for (int nt = 0; nt < 8; nt++) {
            of[nt][0] *= corr0; of[nt][1] *= corr0;
            of[nt][2] *= corr1; of[nt][3] *= corr1;
        }

        // ---- O += P @ V (V in token layout, trans ldmatrix) ----
        #pragma unroll
        for (int u = 0; u < 4; u++) {
            uint32_t pH[4], pL[4];
            split_pair(sf[2 * u][0],     sf[2 * u][1],     pH[0], pL[0]);
            split_pair(sf[2 * u][2],     sf[2 * u][3],     pH[1], pL[1]);
            split_pair(sf[2 * u + 1][0], sf[2 * u + 1][1], pH[2], pL[2]);
            split_pair(sf[2 * u + 1][2], sf[2 * u + 1][3], pH[3], pL[3]);
            const uint32_t vrow = smb +
                (uint32_t)((base + 4608 + (u * 16 + trow_sel) * 36) * 4);
            #pragma unroll
            for (int nt = 0; nt < 8; nt++) {
                uint32_t bH[2], bL[2];
                ldsm_x2_t(bH, vrow + (uint32_t)(nt * 16));
                ldsm_x2_t(bL, vrow + (uint32_t)(2304 * 4 + nt * 16));
                mmabf_x3(of[nt], pH, pL, bH, bL);
            }
        }
        __syncthreads();
        buf ^= 1;
    }

    // epilogue: packed hi/lo O out ([tok][INNER/2 words])
    const float inv0 = 1.f / lrow0, inv1 = 1.f / lrow1;
    const int qa = q0 + pr + g;
    const size_t ro0 = ((size_t)(b * 2048 + qa)) * 256;
    const size_t ro1 = ro0 + 8 * 256;
    #pragma unroll
    for (int nt = 0; nt < 8; nt++) {
        const int w = h * 32 + nt * 4 + t;
        uint32_t hh, ll;
        split_pair(of[nt][0] * inv0, of[nt][1] * inv0, hh, ll);
        OH[ro0 + w] = hh; OL[ro0 + w] = ll;
        split_pair(of[nt][2] * inv1, of[nt][3] * inv1, hh, ll);
        OH[ro1 + w] = hh; OL[ro1 + w] = ll;
    }
}

// ----------------------------------------------------------------------------
// kernel_launch — 4 launches total.
// Inputs: 0=x, 1=context, 2=mask (int32), 3=Wq, 4=Wk, 5=Wv, 6=Wo, 7=bo
// ----------------------------------------------------------------------------
extern "C" void kernel_launch(void* const* d_in, const int* in_sizes, int n_in,
                              void* d_out, int out_size)
{
    const float* x    = (const float*)d_in[0];
    const float* ctx  = (const float*)d_in[1];
    const int*   mask = (const int*)d_in[2];
    const float* Wq   = (const float*)d_in[3];
    const float* Wk   = (const float*)d_in[4];
    const float* Wv   = (const float*)d_in[5];
    const float* Wo   = (const float*)d_in[6];
    const float* bo   = (const float*)d_in[7];
    float* out = (float*)d_out;

    uint32_t *xH, *xL, *cH, *cL, *WqH, *WqL, *WkH, *WkL, *WvH, *WvL, *WoH, *WoL;
    uint32_t *QH, *QL, *KH, *KL, *VH, *VL, *OH2, *OL2;
    int *pidx, *pcnt;
    cudaGetSymbolAddress((void**)&xH, g_xH);   cudaGetSymbolAddress((void**)&xL, g_xL);
    cudaGetSymbolAddress((void**)&cH, g_cH);   cudaGetSymbolAddress((void**)&cL, g_cL);
    cudaGetSymbolAddress((void**)&WqH, g_WqH); cudaGetSymbolAddress((void**)&WqL, g_WqL);
    cudaGetSymbolAddress((void**)&WkH, g_WkH); cudaGetSymbolAddress((void**)&WkL, g_WkL);
    cudaGetSymbolAddress((void**)&WvH, g_WvH); cudaGetSymbolAddress((void**)&WvL, g_WvL);
    cudaGetSymbolAddress((void**)&WoH, g_WoH); cudaGetSymbolAddress((void**)&WoL, g_WoL);
    cudaGetSymbolAddress((void**)&QH, g_QH);   cudaGetSymbolAddress((void**)&QL, g_QL);
    cudaGetSymbolAddress((void**)&KH, g_KH);   cudaGetSymbolAddress((void**)&KL, g_KL);
    cudaGetSymbolAddress((void**)&VH, g_VH);   cudaGetSymbolAddress((void**)&VL, g_VL);
    cudaGetSymbolAddress((void**)&OH2, g_OH2); cudaGetSymbolAddress((void**)&OL2, g_OL2);
    cudaGetSymbolAddress((void**)&pidx, g_idx);
    cudaGetSymbolAddress((void**)&pcnt, g_cnt);

    cudaFuncSetAttribute(proj_kernel, cudaFuncAttributeMaxDynamicSharedMemorySize,
                         2 * GB * 4);
    cudaFuncSetAttribute(out_gemm, cudaFuncAttributeMaxDynamicSharedMemorySize,
                         2 * GB * 4);
    cudaFuncSetAttribute(flash_cp, cudaFuncAttributeMaxDynamicSharedMemorySize,
                         FLASH_SMEM_BYTES);

    // 1) all preprocessing in one launch
    prep_kernel<<<PREP_NB, 256>>>(x, ctx, mask, Wq, Wk, Wv, Wo,
                                  xH, xL, cH, cL,
                                  WqH, WqL, WkH, WkL, WvH, WvL, WoH, WoL,
                                  pidx, pcnt);

    // 2) all three projections in one launch (packed epilogues for Q, K, V)
    {
        dim3 gp(512 / 128, 8192 / 128, 3);
        proj_kernel<<<gp, 256, 2 * GB * 4>>>(xH, xL, cH, cL,
                                             WqH, WqL, WkH, WkL, WvH, WvL,
                                             QH, QL, KH, KL, VH, VL);
    }

    // 3) flash attention over compacted keys (K and V both gathered by idx)
    {
        dim3 grid(NQ / 128, BSZ * HEADS);
        flash_cp<<<grid, 256, FLASH_SMEM_BYTES>>>(QH, QL, KH, KL, VH, VL,
                                                  pidx, pcnt, OH2, OL2);
    }
    // 4) out = O @ Wo + bo
    {
        dim3 go(1024 / 128, 8192 / 128);
        out_gemm<<<go, 256, 2 * GB * 4>>>(OH2, OL2, WoH, WoL, out, bo);
    }
}

// round 17
// speedup vs baseline: 1.0356x; 1.0356x over previous
#include <cuda_runtime.h>
#include <math.h>
#include <stdint.h>

// Problem constants
#define BSZ   4
#define NQ    2048
#define MK    2048
#define DIMX  1024
#define CTXD  1024
#define HEADS 8
#define DHEAD 64
#define INNER 512   // HEADS * DHEAD

// ============================================================================
// Packed bf16 hi/lo scratch in gmem (allocation-free: __device__ globals)
// ============================================================================
__device__ uint32_t g_xH[(size_t)8192 * 512], g_xL[(size_t)8192 * 512];
__device__ uint32_t g_cH[(size_t)8192 * 512], g_cL[(size_t)8192 * 512];
__device__ uint32_t g_WqH[512 * 512],  g_WqL[512 * 512];
__device__ uint32_t g_WkH[512 * 512],  g_WkL[512 * 512];
__device__ uint32_t g_WvH[512 * 512],  g_WvL[512 * 512];
__device__ uint32_t g_WoH[1024 * 256], g_WoL[1024 * 256];
__device__ uint32_t g_QH[(size_t)32 * 2048 * 32], g_QL[(size_t)32 * 2048 * 32];
__device__ uint32_t g_KH[(size_t)32 * 2048 * 32], g_KL[(size_t)32 * 2048 * 32];
__device__ uint32_t g_VtH[(size_t)32 * 64 * 1024], g_VtL[(size_t)32 * 64 * 1024];
__device__ float    g_Vf[(size_t)8192 * 512];
__device__ uint32_t g_OH2[(size_t)8192 * 256], g_OL2[(size_t)8192 * 256];
__device__ int      g_idx[BSZ * MK];
__device__ int      g_cnt[BSZ];

// ============================================================================
// bf16 x3 helpers, ldmatrix, cp.async
// ============================================================================
__device__ __forceinline__ uint32_t pack_bf16x2(float e0, float e1) {
    uint32_t r;
    asm("cvt.rn.bf16x2.f32 %0, %1, %2;" : "=r"(r) : "f"(e1), "f"(e0));
    return r;
}
__device__ __forceinline__ void split_pair(float x0, float x1,
                                           uint32_t& hi, uint32_t& lo) {
    hi = pack_bf16x2(x0, x1);
    float h0 = __uint_as_float(hi << 16);
    float h1 = __uint_as_float(hi & 0xffff0000u);
    lo = pack_bf16x2(x0 - h0, x1 - h1);
}
__device__ __forceinline__ void mmabf(float c[4], const uint32_t a[4],
                                      const uint32_t b[2]) {
    asm volatile(
        "mma.sync.aligned.m16n8k16.row.col.f32.bf16.bf16.f32 "
        "{%0,%1,%2,%3},{%4,%5,%6,%7},{%8,%9},{%0,%1,%2,%3};"
        : "+f"(c[0]), "+f"(c[1]), "+f"(c[2]), "+f"(c[3])
        : "r"(a[0]), "r"(a[1]), "r"(a[2]), "r"(a[3]), "r"(b[0]), "r"(b[1]));
}
__device__ __forceinline__ void mmabf_x3(float c[4],
                                         const uint32_t aH[4], const uint32_t aL[4],
                                         const uint32_t bH[2], const uint32_t bL[2]) {
    mmabf(c, aH, bH);
    mmabf(c, aH, bL);
    mmabf(c, aL, bH);
}
__device__ __forceinline__ void ldsm_x4(uint32_t* r, uint32_t a) {
    asm volatile("ldmatrix.sync.aligned.m8n8.x4.shared.b16 {%0,%1,%2,%3}, [%4];"
                 : "=r"(r[0]), "=r"(r[1]), "=r"(r[2]), "=r"(r[3]) : "r"(a));
}
__device__ __forceinline__ void ldsm_x2(uint32_t* r, uint32_t a) {
    asm volatile("ldmatrix.sync.aligned.m8n8.x2.shared.b16 {%0,%1}, [%2];"
                 : "=r"(r[0]), "=r"(r[1]) : "r"(a));
}
__device__ __forceinline__ uint32_t smem_u32(const void* p) {
    uint32_t a;
    asm("{ .reg .u64 t; cvta.to.shared.u64 t, %1; cvt.u32.u64 %0, t; }"
        : "=r"(a) : "l"(p));
    return a;
}
__device__ __forceinline__ void cpa16(uint32_t sa, const void* g) {
    asm volatile("cp.async.cg.shared.global [%0], [%1], 16;"
                 :: "r"(sa), "l"(g) : "memory");
}
__device__ __forceinline__ void cpa16z(uint32_t sa, const void* g, bool valid) {
    int sz = valid ? 16 : 0;
    asm volatile("cp.async.cg.shared.global [%0], [%1], 16, %2;"
                 :: "r"(sa), "l"(g), "r"(sz) : "memory");
}
#define CP_COMMIT() asm volatile("cp.async.commit_group;" ::: "memory")
#define CP_WAIT0()  asm volatile("cp.async.wait_group 0;"  ::: "memory")

// ============================================================================
// prep_kernel: ONE launch covering all independent preprocessing.
// ============================================================================
#define PREP_C0  8192
#define PREP_WQ  16384
#define PREP_WK  16448
#define PREP_WV  16512
#define PREP_WO  16576
#define PREP_CM  16640
#define PREP_NB  16644

__device__ __forceinline__ void repack_a_body(const float* __restrict__ A,
                                              uint32_t* __restrict__ H,
                                              uint32_t* __restrict__ L,
                                              int blk, int tid)
{
    int i = blk * 256 + tid;
    float4 a = ((const float4*)A)[i];
    uint32_t h0, l0, h1, l1;
    split_pair(a.x, a.y, h0, l0);
    split_pair(a.z, a.w, h1, l1);
    H[2 * i] = h0; H[2 * i + 1] = h1;
    L[2 * i] = l0; L[2 * i + 1] = l1;
}

__device__ __forceinline__ void repack_w_body(const float* __restrict__ W,
                                              uint32_t* __restrict__ H,
                                              uint32_t* __restrict__ L,
                                              int K, int N, int k0, int n0,
                                              float SM[128][68], int tid)
{
    #pragma unroll
    for (int j = 0; j < 8; j++) {
        int idx = tid + j * 256;
        int r = idx >> 4, c4 = (idx & 15) * 4;
        *(float4*)&SM[r][c4] = *(const float4*)(W + (size_t)(k0 + r) * N + n0 + c4);
    }
    __syncthreads();
    #pragma unroll
    for (int j = 0; j < 16; j++) {
        int idx = tid + j * 256;
        int n = idx >> 6, kp = idx & 63;
        uint32_t h, l;
        split_pair(SM[2 * kp][n], SM[2 * kp + 1][n], h, l);
        size_t d = (size_t)(n0 + n) * (K / 2) + k0 / 2 + kp;
        H[d] = h; L[d] = l;
    }
}

__global__ __launch_bounds__(256)
void prep_kernel(const float* __restrict__ x, const float* __restrict__ ctx,
                 const int* __restrict__ mask,
                 const float* __restrict__ Wq, const float* __restrict__ Wk,
                 const float* __restrict__ Wv, const float* __restrict__ Wo,
                 uint32_t* xH, uint32_t* xL, uint32_t* cH, uint32_t* cL,
                 uint32_t* WqH, uint32_t* WqL, uint32_t* WkH, uint32_t* WkL,
                 uint32_t* WvH, uint32_t* WvL, uint32_t* WoH, uint32_t* WoL,
                 int* __restrict__ idxOut, int* __restrict__ cntOut)
{
    __shared__ float SM[128][68];
    const int bid = blockIdx.x, tid = threadIdx.x;

    if (bid < PREP_C0) {
        repack_a_body(x, xH, xL, bid, tid);
    } else if (bid < PREP_WQ) {
        repack_a_body(ctx, cH, cL, bid - PREP_C0, tid);
    } else if (bid < PREP_WK) {
        int b = bid - PREP_WQ;
        repack_w_body(Wq, WqH, WqL, 1024, 512, (b & 7) * 128, (b >> 3) * 64, SM, tid);
    } else if (bid < PREP_WV) {
        int b = bid - PREP_WK;
        repack_w_body(Wk, WkH, WkL, 1024, 512, (b & 7) * 128, (b >> 3) * 64, SM, tid);
    } else if (bid < PREP_WO) {
        int b = bid - PREP_WV;
        repack_w_body(Wv, WvH, WvL, 1024, 512, (b & 7) * 128, (b >> 3) * 64, SM, tid);
    } else if (bid < PREP_CM) {
        int b = bid - PREP_WO;
        repack_w_body(Wo, WoH, WoL, 512, 1024, (b & 3) * 128, (b >> 2) * 64, SM, tid);
    } else {
        // compact_mask body (1 block per batch)
        int* ws = (int*)&SM[0][0];
        const int b = bid - PREP_CM;
        const int lane = tid & 31, w = tid >> 5;
        const int* mb = mask + b * MK;
        int loc[8], c = 0;
        #pragma unroll
        for (int j = 0; j < 8; j++) {
            loc[j] = (mb[tid * 8 + j] != 0);
            c += loc[j];
        }
        int pre = c;
        #pragma unroll
        for (int off = 1; off < 32; off <<= 1) {
            int v = __shfl_up_sync(0xffffffffu, pre, off);
            if (lane >= off) pre += v;
        }
        if (lane == 31) ws[w] = pre;
        __syncthreads();
        if (tid == 0) {
            int s = 0;
            #pragma unroll
            for (int i = 0; i < 8; i++) { int t2 = ws[i]; ws[i] = s; s += t2; }
            cntOut[b] = s;
        }
        __syncthreads();
        int start = ws[w] + pre - c;
        #pragma unroll
        for (int j = 0; j < 8; j++)
            if (loc[j]) idxOut[b * MK + start++] = tid * 8 + j;
    }
}

// ============================================================================
// repack_v (key gather/compaction): fp32 V [B*2048][512] -> per-(b,h)
// transposed packed [64 d][1024 keypair], keys reordered by idx, zero-filled
// past cnt. grid (2048/128, 32)
// ============================================================================
__global__ __launch_bounds__(256)
void repack_v(const float* __restrict__ V, uint32_t* __restrict__ H,
              uint32_t* __restrict__ L, const int* __restrict__ idx,
              const int* __restrict__ cnt)
{
    __shared__ float SM[128][68];
    const int tid = threadIdx.x;
    const int bh = blockIdx.y, b = bh >> 3, h = bh & 7;
    const int k0 = blockIdx.x * 128;
    const int cntb = cnt[b];
    #pragma unroll
    for (int j = 0; j < 8; j++) {
        int i2 = tid + j * 256;
        int r = i2 >> 4, c4 = (i2 & 15) * 4;
        float4 v = make_float4(0.f, 0.f, 0.f, 0.f);
        const int tok_i = k0 + r;
        if (tok_i < cntb) {
            const int tok = idx[b * MK + tok_i];
            v = *(const float4*)(V + (size_t)(b * 2048 + tok) * 512 + h * 64 + c4);
        }
        *(float4*)&SM[r][c4] = v;
    }
    __syncthreads();
    #pragma unroll
    for (int j = 0; j < 16; j++) {
        int i2 = tid + j * 256;
        int d = i2 >> 6, kp = i2 & 63;
        uint32_t hh, ll;
        split_pair(SM[2 * kp][d], SM[2 * kp + 1][d], hh, ll);
        size_t dst = ((size_t)bh * 64 + d) * 1024 + k0 / 2 + kp;
        H[dst] = hh; L[dst] = ll;
    }
}

// ============================================================================
// Shared GEMM mainloop (BM=128, BN=128, BK=32; 256 thr, warp 32x64).
// Single-sync double-buffer: wait0 -> sync -> stage(next) -> compute(cur).
// ============================================================================
#define GB 10240   // words per stage buffer

struct GemmCtx {
    uint32_t smb;
    int tid, lane, warp, wm, wn, g, t;
    int arow_sel, acol_sel, brow_sel, bcol_sel;
    int srow, sseg;
};
__device__ __forceinline__ void gemm_init(GemmCtx& c) {
    c.tid = threadIdx.x;
    c.lane = c.tid & 31; c.warp = c.tid >> 5;
    c.wm = c.warp & 3; c.wn = c.warp >> 2;
    c.g = c.lane >> 2; c.t = c.lane & 3;
    c.arow_sel = (c.lane & 7) + (c.lane & 8);
    c.acol_sel = (c.lane & 16) ? 4 : 0;
    c.brow_sel = c.lane & 7;
    c.bcol_sel = (c.lane & 8) ? 4 : 0;
    c.srow = c.tid >> 2; c.sseg = c.tid & 3;
}
__device__ __forceinline__ void gemm_stage(const GemmCtx& c,
                                           const uint32_t* AH, const uint32_t* AL,
                                           const uint32_t* BH, const uint32_t* BL,
                                           int m0, int n0, int Kw,
                                           int buf, int k0) {
    const int base = buf * GB;
    #pragma unroll
    for (int j = 0; j < 2; j++) {
        const int row = c.srow + j * 64;
        const uint32_t sa = c.smb + (uint32_t)((base + row * 20 + c.sseg * 4) * 4);
        const size_t ga = (size_t)(m0 + row) * Kw + (k0 >> 1) + c.sseg * 4;
        cpa16(sa, AH + ga);
        cpa16(sa + 2560 * 4, AL + ga);
        const size_t gb = (size_t)(n0 + row) * Kw + (k0 >> 1) + c.sseg * 4;
        cpa16(sa + 5120 * 4, BH + gb);
        cpa16(sa + 7680 * 4, BL + gb);
    }
}
__device__ __forceinline__ void gemm_mainloop(const GemmCtx& c,
                                              const uint32_t* AH, const uint32_t* AL,
                                              const uint32_t* BH, const uint32_t* BL,
                                              int m0, int n0, int K,
                                              float acc[2][8][4]) {
    const int Kw = K >> 1;
    #pragma unroll
    for (int mt = 0; mt < 2; mt++)
        #pragma unroll
        for (int nt = 0; nt < 8; nt++)
            #pragma unroll
            for (int i = 0; i < 4; i++) acc[mt][nt][i] = 0.f;

    gemm_stage(c, AH, AL, BH, BL, m0, n0, Kw, 0, 0);
    CP_COMMIT();

    int buf = 0;
    for (int k0 = 0; k0 < K; k0 += 32) {
        CP_WAIT0();
        __syncthreads();
        if (k0 + 32 < K) {
            gemm_stage(c, AH, AL, BH, BL, m0, n0, Kw, buf ^ 1, k0 + 32);
            CP_COMMIT();
        }

        const int base = buf * GB;
        #pragma unroll
        for (int s = 0; s < 2; s++) {
            uint32_t aH[2][4], aL[2][4];
            #pragma unroll
            for (int mt = 0; mt < 2; mt++) {
                const uint32_t aoff = c.smb +
                    (uint32_t)((base + (c.wm * 32 + mt * 16 + c.arow_sel) * 20 +
                                s * 8 + c.acol_sel) * 4);
                ldsm_x4(aH[mt], aoff);
                ldsm_x4(aL[mt], aoff + 2560 * 4);
            }
            #pragma unroll
            for (int nt = 0; nt < 8; nt++) {
                const uint32_t boff = c.smb +
                    (uint32_t)((base + (c.wn * 64 + nt * 8 + c.brow_sel) * 20 +
                                s * 8 + c.bcol_sel) * 4);
                uint32_t bH[2], bL[2];
                ldsm_x2(bH, boff + 5120 * 4);
                ldsm_x2(bL, boff + 7680 * 4);
                mmabf_x3(acc[0][nt], aH[0], aL[0], bH, bL);
                mmabf_x3(acc[1][nt], aH[1], aL[1], bH, bL);
            }
        }
        buf ^= 1;
    }
}

// ============================================================================
// proj_kernel: ONE launch for all 3 projections (blockIdx.z = 0:Q, 1:K, 2:V).
// Q/K epilogue -> packed [b,h][tok][dpair]; V epilogue -> fp32 Vf.
// grid (512/128, 8192/128, 3)
// ============================================================================
__global__ __launch_bounds__(256, 2)
void proj_kernel(const uint32_t* __restrict__ xH, const uint32_t* __restrict__ xL,
                 const uint32_t* __restrict__ cH, const uint32_t* __restrict__ cL,
                 const uint32_t* __restrict__ WqH, const uint32_t* __restrict__ WqL,
                 const uint32_t* __restrict__ WkH, const uint32_t* __restrict__ WkL,
                 const uint32_t* __restrict__ WvH, const uint32_t* __restrict__ WvL,
                 uint32_t* __restrict__ QH, uint32_t* __restrict__ QL,
                 uint32_t* __restrict__ KH, uint32_t* __restrict__ KL,
                 float* __restrict__ Vf)
{
    extern __shared__ uint32_t gs[];
    GemmCtx c;
    gemm_init(c);
    c.smb = smem_u32(gs);

    const int z = blockIdx.z;
    const int m0 = blockIdx.y * 128, n0 = blockIdx.x * 128;
    const uint32_t *AH, *AL, *BH, *BL;
    if (z == 0)      { AH = xH; AL = xL; BH = WqH; BL = WqL; }
    else if (z == 1) { AH = cH; AL = cL; BH = WkH; BL = WkL; }
    else             { AH = cH; AL = cL; BH = WvH; BL = WvL; }

    float acc[2][8][4];
    gemm_mainloop(c, AH, AL, BH, BL, m0, n0, 1024, acc);

    if (z == 2) {
        #pragma unroll
        for (int mt = 0; mt < 2; mt++) {
            const int r0 = m0 + c.wm * 32 + mt * 16 + c.g;
            #pragma unroll
            for (int nt = 0; nt < 8; nt++) {
                const int c0 = n0 + c.wn * 64 + nt * 8 + c.t * 2;
                *(float2*)(Vf + (size_t)r0 * 512 + c0) =
                    make_float2(acc[mt][nt][0], acc[mt][nt][1]);
                *(float2*)(Vf + (size_t)(r0 + 8) * 512 + c0) =
                    make_float2(acc[mt][nt][2], acc[mt][nt][3]);
            }
        }
    } else {
        uint32_t* OH = (z == 0) ? QH : KH;
        uint32_t* OL = (z == 0) ? QL : KL;
        #pragma unroll
        for (int mt = 0; mt < 2; mt++) {
            const int r0 = m0 + c.wm * 32 + mt * 16 + c.g;
            const int b = r0 >> 11;
            #pragma unroll
            for (int nt = 0; nt < 8; nt++) {
                const int c0 = n0 + c.wn * 64 + nt * 8 + c.t * 2;
                const int h = c0 >> 6, w = (c0 & 63) >> 1;
                uint32_t hh, ll;
                split_pair(acc[mt][nt][0], acc[mt][nt][1], hh, ll);
                size_t d0 = ((size_t)(b * 8 + h) * 2048 + (r0 & 2047)) * 32 + w;
                OH[d0] = hh; OL[d0] = ll;
                split_pair(acc[mt][nt][2], acc[mt][nt][3], hh, ll);
                size_t d1 = d0 + 8 * 32;
                OH[d1] = hh; OL[d1] = ll;
            }
        }
    }
}

// ============================================================================
// out_gemm: out = O @ Wo + bo (packed operands), fp32 out.
// grid (1024/128, 8192/128)
// ============================================================================
__global__ __launch_bounds__(256, 2)
void out_gemm(const uint32_t* __restrict__ AH, const uint32_t* __restrict__ AL,
              const uint32_t* __restrict__ BH, const uint32_t* __restrict__ BL,
              float* __restrict__ C, const float* __restrict__ bias)
{
    extern __shared__ uint32_t gs[];
    GemmCtx c;
    gemm_init(c);
    c.smb = smem_u32(gs);
    const int m0 = blockIdx.y * 128, n0 = blockIdx.x * 128;

    float acc[2][8][4];
    gemm_mainloop(c, AH, AL, BH, BL, m0, n0, 512, acc);

    #pragma unroll
    for (int mt = 0; mt < 2; mt++) {
        const int r0 = m0 + c.wm * 32 + mt * 16 + c.g;
        #pragma unroll
        for (int nt = 0; nt < 8; nt++) {
            const int c0 = n0 + c.wn * 64 + nt * 8 + c.t * 2;
            float b0v = bias[c0], b1v = bias[c0 + 1];
            *(float2*)(C + (size_t)r0 * 1024 + c0) =
                make_float2(acc[mt][nt][0] + b0v, acc[mt][nt][1] + b1v);
            *(float2*)(C + (size_t)(r0 + 8) * 1024 + c0) =
                make_float2(acc[mt][nt][2] + b0v, acc[mt][nt][3] + b1v);
        }
    }
}

// ============================================================================
// flash_cp: bf16 x3, P in registers, cp.async double-buffered, compacted keys.
// Single-sync schedule: wait0 -> sync -> stage(next) -> compute(cur).
// Smem words: Qh[0..4607] Ql[4608..9215]; per buf (9216 + buf*9216):
//   Kh +0, Kl +2304, Vh +4608, Vl +6912 (each 64 rows x 36 stride).
// ============================================================================
#define FL_KV    9216
#define FL_BUF   9216
#define FLASH_SMEM_BYTES ((FL_KV + 2 * FL_BUF) * 4)

__global__ __launch_bounds__(256, 2)
void flash_cp(const uint32_t* __restrict__ QHg, const uint32_t* __restrict__ QLg,
              const uint32_t* __restrict__ KHg, const uint32_t* __restrict__ KLg,
              const uint32_t* __restrict__ VHg, const uint32_t* __restrict__ VLg,
              const int* __restrict__ idx, const int* __restrict__ cnt,
              uint32_t* __restrict__ OH, uint32_t* __restrict__ OL)
{
    extern __shared__ uint32_t fsm[];
    const uint32_t smb = smem_u32(fsm);

    const int bh = blockIdx.y;
    const int b = bh >> 3, h = bh & 7;
    const int q0 = blockIdx.x * 128;

    const int tid = threadIdx.x;
    const int lane = tid & 31, warp = tid >> 5;
    const int g = lane >> 2, t = lane & 3;
    const int pr = warp * 16;

    const int arow_sel = (lane & 7) + (lane & 8);
    const int acol_sel = (lane & 16) ? 4 : 0;
    const int brow_sel = lane & 7;
    const int bcol_sel = (lane & 8) ? 4 : 0;

    const int cntb = cnt[b];
    const int Mp = (cntb + 63) & ~63;
    const int* gidx = idx + b * MK;

    auto stageKV = [&](int nb, int kt2) {
        const int base = FL_KV + nb * FL_BUF;
        #pragma unroll
        for (int j = 0; j < 2; j++) {
            const int i2 = tid + j * 256;
            const int r = i2 >> 3, sg = i2 & 7;
            const int tok_i = kt2 + r;
            const bool valid = tok_i < cntb;
            const int tok = valid ? gidx[tok_i] : 0;
            const uint32_t sa = smb + (uint32_t)((base + r * 36 + sg * 4) * 4);
            const size_t gk = ((size_t)bh * 2048 + tok) * 32 + sg * 4;
            cpa16z(sa, KHg + gk, valid);
            cpa16z(sa + 2304 * 4, KLg + gk, valid);
            const size_t gv = ((size_t)bh * 64 + r) * 1024 + (kt2 >> 1) + sg * 4;
            cpa16(sa + 4608 * 4, VHg + gv);
            cpa16(sa + 6912 * 4, VLg + gv);
        }
    };

    // prologue: stage Q + tile 0
    #pragma unroll
    for (int j = 0; j < 4; j++) {
        const int i2 = tid + j * 256;
        const int row = i2 >> 3, seg = i2 & 7;
        const uint32_t sa = smb + (uint32_t)((row * 36 + seg * 4) * 4);
        const size_t gq = ((size_t)bh * 2048 + q0 + row) * 32 + seg * 4;
        cpa16(sa, QHg + gq);
        cpa16(sa + 4608 * 4, QLg + gq);
    }
    stageKV(0, 0);
    CP_COMMIT();

    float of[8][4];
    #pragma unroll
    for (int nt = 0; nt < 8; nt++)
        #pragma unroll
        for (int i = 0; i < 4; i++) of[nt][i] = 0.f;
    float mrow0 = -3.0e38f, mrow1 = -3.0e38f, lrow0 = 0.f, lrow1 = 0.f;
    const float scale = 0.125f;

    int buf = 0;
    for (int kt = 0; kt < Mp; kt += 64) {
        CP_WAIT0();
        __syncthreads();
        if (kt + 64 < Mp) {
            stageKV(buf ^ 1, kt + 64);
            CP_COMMIT();
        }

        const int base = FL_KV + buf * FL_BUF;
        const int limit = cntb - kt;

        // ---- S = Q K^T ----
        float sf[8][4];
        #pragma unroll
        for (int nt = 0; nt < 8; nt++)
            #pragma unroll
            for (int i = 0; i < 4; i++) sf[nt][i] = 0.f;

        #pragma unroll
        for (int s = 0; s < 4; s++) {
            uint32_t aH[4], aL[4];
            const uint32_t qoff = smb +
                (uint32_t)(((pr + arow_sel) * 36 + s * 8 + acol_sel) * 4);
            ldsm_x4(aH, qoff);
            ldsm_x4(aL, qoff + 4608 * 4);
            #pragma unroll
            for (int nt = 0; nt < 8; nt++) {
                const uint32_t koff = smb +
                    (uint32_t)((base + (nt * 8 + brow_sel) * 36 + s * 8 + bcol_sel) * 4);
                uint32_t bH[2], bL[2];
                ldsm_x2(bH, koff);
                ldsm_x2(bL, koff + 2304 * 4);
                mmabf_x3(sf[nt], aH, aL, bH, bL);
            }
        }

        // ---- scale + validity + online softmax ----
        float mx0 = -3.0e38f, mx1 = -3.0e38f;
        #pragma unroll
        for (int nt = 0; nt < 8; nt++) {
            const int c0 = nt * 8 + 2 * t;
            float mk0 = (c0     < limit) ? 0.f : -1.0e30f;
            float mk1 = (c0 + 1 < limit) ? 0.f : -1.0e30f;
            sf[nt][0] = sf[nt][0] * scale + mk0;
            sf[nt][1] = sf[nt][1] * scale + mk1;
            sf[nt][2] = sf[nt][2] * scale + mk0;
            sf[nt][3] = sf[nt][3] * scale + mk1;
            mx0 = fmaxf(mx0, fmaxf(sf[nt][0], sf[nt][1]));
            mx1 = fmaxf(mx1, fmaxf(sf[nt][2], sf[nt][3]));
        }
        mx0 = fmaxf(mx0, __shfl_xor_sync(0xffffffffu, mx0, 1));
        mx0 = fmaxf(mx0, __shfl_xor_sync(0xffffffffu, mx0, 2));
        mx1 = fmaxf(mx1, __shfl_xor_sync(0xffffffffu, mx1, 1));
        mx1 = fmaxf(mx1, __shfl_xor_sync(0xffffffffu, mx1, 2));

        const float mn0 = fmaxf(mrow0, mx0), mn1 = fmaxf(mrow1, mx1);
        const float corr0 = __expf(mrow0 - mn0), corr1 = __expf(mrow1 - mn1);
        float ls0 = 0.f, ls1 = 0.f;
        #pragma unroll
        for (int nt = 0; nt < 8; nt++) {
            sf[nt][0] = __expf(sf[nt][0] - mn0);
            sf[nt][1] = __expf(sf[nt][1] - mn0);
            sf[nt][2] = __expf(sf[nt][2] - mn1);
            sf[nt][3] = __expf(sf[nt][3] - mn1);
            ls0 += sf[nt][0] + sf[nt][1];
            ls1 += sf[nt][2] + sf[nt][3];
        }
        ls0 += __shfl_xor_sync(0xffffffffu, ls0, 1);
        ls0 += __shfl_xor_sync(0xffffffffu, ls0, 2);
        ls1 += __shfl_xor_sync(0xffffffffu, ls1, 1);
        ls1 += __shfl_xor_sync(0xffffffffu, ls1, 2);

        lrow0 = lrow0 * corr0 + ls0; mrow0 = mn0;
        lrow1 = lrow1 * corr1 + ls1; mrow1 = mn1;

        #pragma unroll
        for (int nt = 0; nt < 8; nt++) {
            of[nt][0] *= corr0; of[nt][1] *= corr0;
            of[nt][2] *= corr1; of[nt][3] *= corr1;
        }

        // ---- O += P @ V ----
        #pragma unroll
        for (int u = 0; u < 4; u++) {
            uint32_t pH[4], pL[4];
            split_pair(sf[2 * u][0],     sf[2 * u][1],     pH[0], pL[0]);
            split_pair(sf[2 * u][2],     sf[2 * u][3],     pH[1], pL[1]);
            split_pair(sf[2 * u + 1][0], sf[2 * u + 1][1], pH[2], pL[2]);
            split_pair(sf[2 * u + 1][2], sf[2 * u + 1][3], pH[3], pL[3]);
            #pragma unroll
            for (int nt = 0; nt < 8; nt++) {
                const uint32_t voff = smb +
                    (uint32_t)((base + (nt * 8 + brow_sel) * 36 + u * 8 + bcol_sel) * 4);
                uint32_t bH[2], bL[2];
                ldsm_x2(bH, voff + 4608 * 4);
                ldsm_x2(bL, voff + 6912 * 4);
                mmabf_x3(of[nt], pH, pL, bH, bL);
            }
        }
        buf ^= 1;
    }

    // epilogue: packed hi/lo O out ([tok][INNER/2 words])
    const float inv0 = 1.f / lrow0, inv1 = 1.f / lrow1;
    const int qa = q0 + pr + g;
    const size_t ro0 = ((size_t)(b * 2048 + qa)) * 256;
    const size_t ro1 = ro0 + 8 * 256;
    #pragma unroll
    for (int nt = 0; nt < 8; nt++) {
        const int w = h * 32 + nt * 4 + t;
        uint32_t hh, ll;
        split_pair(of[nt][0] * inv0, of[nt][1] * inv0, hh, ll);
        OH[ro0 + w] = hh; OL[ro0 + w] = ll;
        split_pair(of[nt][2] * inv1, of[nt][3] * inv1, hh, ll);
        OH[ro1 + w] = hh; OL[ro1 + w] = ll;
    }
}

// ----------------------------------------------------------------------------
// kernel_launch — 5 launches total.
// Inputs: 0=x, 1=context, 2=mask (int32), 3=Wq, 4=Wk, 5=Wv, 6=Wo, 7=bo
// ----------------------------------------------------------------------------
extern "C" void kernel_launch(void* const* d_in, const int* in_sizes, int n_in,
                              void* d_out, int out_size)
{
    const float* x    = (const float*)d_in[0];
    const float* ctx  = (const float*)d_in[1];
    const int*   mask = (const int*)d_in[2];
    const float* Wq   = (const float*)d_in[3];
    const float* Wk   = (const float*)d_in[4];
    const float* Wv   = (const float*)d_in[5];
    const float* Wo   = (const float*)d_in[6];
    const float* bo   = (const float*)d_in[7];
    float* out = (float*)d_out;

    uint32_t *xH, *xL, *cH, *cL, *WqH, *WqL, *WkH, *WkL, *WvH, *WvL, *WoH, *WoL;
    uint32_t *QH, *QL, *KH, *KL, *VtH, *VtL, *OH2, *OL2;
    float *Vf;
    int *pidx, *pcnt;
    cudaGetSymbolAddress((void**)&xH, g_xH);   cudaGetSymbolAddress((void**)&xL, g_xL);
    cudaGetSymbolAddress((void**)&cH, g_cH);   cudaGetSymbolAddress((void**)&cL, g_cL);
    cudaGetSymbolAddress((void**)&WqH, g_WqH); cudaGetSymbolAddress((void**)&WqL, g_WqL);
    cudaGetSymbolAddress((void**)&WkH, g_WkH); cudaGetSymbolAddress((void**)&WkL, g_WkL);
    cudaGetSymbolAddress((void**)&WvH, g_WvH); cudaGetSymbolAddress((void**)&WvL, g_WvL);
    cudaGetSymbolAddress((void**)&WoH, g_WoH); cudaGetSymbolAddress((void**)&WoL, g_WoL);
    cudaGetSymbolAddress((void**)&QH, g_QH);   cudaGetSymbolAddress((void**)&QL, g_QL);
    cudaGetSymbolAddress((void**)&KH, g_KH);   cudaGetSymbolAddress((void**)&KL, g_KL);
    cudaGetSymbolAddress((void**)&VtH, g_VtH); cudaGetSymbolAddress((void**)&VtL, g_VtL);
    cudaGetSymbolAddress((void**)&OH2, g_OH2); cudaGetSymbolAddress((void**)&OL2, g_OL2);
    cudaGetSymbolAddress((void**)&Vf, g_Vf);
    cudaGetSymbolAddress((void**)&pidx, g_idx);
    cudaGetSymbolAddress((void**)&pcnt, g_cnt);

    cudaFuncSetAttribute(proj_kernel, cudaFuncAttributeMaxDynamicSharedMemorySize,
                         2 * GB * 4);
    cudaFuncSetAttribute(out_gemm, cudaFuncAttributeMaxDynamicSharedMemorySize,
                         2 * GB * 4);
    cudaFuncSetAttribute(flash_cp, cudaFuncAttributeMaxDynamicSharedMemorySize,
                         FLASH_SMEM_BYTES);

    // 1) all preprocessing in one launch
    prep_kernel<<<PREP_NB, 256>>>(x, ctx, mask, Wq, Wk, Wv, Wo,
                                  xH, xL, cH, cL,
                                  WqH, WqL, WkH, WkL, WvH, WvL, WoH, WoL,
                                  pidx, pcnt);

    // 2) all three projections in one launch
    {
        dim3 gp(512 / 128, 8192 / 128, 3);
        proj_kernel<<<gp, 256, 2 * GB * 4>>>(xH, xL, cH, cL,
                                             WqH, WqL, WkH, WkL, WvH, WvL,
                                             QH, QL, KH, KL, Vf);
    }

    // 3) V transpose + gather
    repack_v<<<dim3(16, 32), 256>>>(Vf, VtH, VtL, pidx, pcnt);

    // 4) flash attention over compacted keys
    {
        dim3 grid(NQ / 128, BSZ * HEADS);
        flash_cp<<<grid, 256, FLASH_SMEM_BYTES>>>(QH, QL, KH, KL, VtH, VtL,
                                                  pidx, pcnt, OH2, OL2);
    }
    // 5) out = O @ Wo + bo
    {
        dim3 go(1024 / 128, 8192 / 128);
        out_gemm<<<go, 256, 2 * GB * 4>>>(OH2, OL2, WoH, WoL, out, bo);
    }
}